// round 2
// baseline (speedup 1.0000x reference)
#include <cuda_runtime.h>
#include <math.h>

#define Bn 16
#define Cn 256
#define Hn 128
#define Wn 128
#define TH 16
#define TW 32
#define KC 4
#define PAD 4
#define NTHREADS 384

// Per-block smem tiles:
//   s_src: KC channels of (TH+8)x(TW+8) source halo tile  = 4*24*40*4 = 15360 B
//   s_tgt: KC channels of TH x TW target tile             = 4*16*32*4 =  8192 B
//   s_red: cross-dh-group sum-of-squares reduction buffer = 3*16*32*4 =  6144 B
__global__ __launch_bounds__(NTHREADS, 1)
void corr_norm_kernel(const float* __restrict__ src,
                      const float* __restrict__ tgt,
                      float* __restrict__ out)
{
    __shared__ __align__(16) float s_src[KC][TH + 8][TW + 8];
    __shared__ __align__(16) float s_tgt[KC][TH][TW];
    __shared__ float s_red[3][TH][TW];

    const int tx = threadIdx.x;            // 0..7  : 4-pixel groups along w
    const int ty = threadIdx.y;            // 0..15 : h within tile
    const int tz = threadIdx.z;            // 0..2  : dh group (3 dh rows each)
    const int tid = tx + 8 * ty + 128 * tz;

    const int b  = blockIdx.z;
    const int h0 = blockIdx.y * TH;
    const int wb = blockIdx.x * TW;

    float* s_srcF = &s_src[0][0][0];
    float* s_tgtF = &s_tgt[0][0][0];

    // ---- precompute prefetch slot addressing (invariant across channel chunks) ----
    int  s_off[10]; bool s_ok[10];
#pragma unroll
    for (int i = 0; i < 10; i++) {
        int g   = tid + i * NTHREADS;                 // flat index into KC*(TH+8)*(TW+8)
        int cc  = g / ((TH + 8) * (TW + 8));
        int rem = g % ((TH + 8) * (TW + 8));
        int r   = rem / (TW + 8);
        int col = rem % (TW + 8);
        int gh = h0 - PAD + r;
        int gw = wb - PAD + col;
        s_ok[i]  = ((unsigned)gh < (unsigned)Hn) && ((unsigned)gw < (unsigned)Wn);
        s_off[i] = s_ok[i] ? (((b * Cn + cc) * Hn + gh) * Wn + gw) : 0;
    }
    int  t_off[6]; bool t_ok[6];
#pragma unroll
    for (int i = 0; i < 6; i++) {
        int g = tid + i * NTHREADS;                   // flat index into KC*TH*TW
        t_ok[i] = g < KC * TH * TW;
        int gg  = t_ok[i] ? g : 0;
        int cc  = gg / (TH * TW);
        int rem = gg % (TH * TW);
        int r   = rem / TW;
        int col = rem % TW;
        t_off[i] = ((b * Cn + cc) * Hn + h0 + r) * Wn + wb + col;
    }

    // ---- prefetch chunk 0 into registers ----
    float pf_s[10], pf_t[6];
#pragma unroll
    for (int i = 0; i < 10; i++) pf_s[i] = s_ok[i] ? __ldg(src + s_off[i]) : 0.f;
#pragma unroll
    for (int i = 0; i < 6; i++)  pf_t[i] = t_ok[i] ? __ldg(tgt + t_off[i]) : 0.f;

    // ---- accumulators: 3 dh rows x 9 dw x 4 pixels = 108 fp32 ----
    float acc[3][9][4];
#pragma unroll
    for (int r = 0; r < 3; r++)
#pragma unroll
        for (int dw = 0; dw < 9; dw++)
#pragma unroll
            for (int p = 0; p < 4; p++) acc[r][dw][p] = 0.f;

    for (int c0 = 0; c0 < Cn; c0 += KC) {
        // commit prefetched registers to shared
#pragma unroll
        for (int i = 0; i < 10; i++) s_srcF[tid + i * NTHREADS] = pf_s[i];
#pragma unroll
        for (int i = 0; i < 6; i++) if (t_ok[i]) s_tgtF[tid + i * NTHREADS] = pf_t[i];
        __syncthreads();

        // issue prefetch for next chunk (overlaps with compute below)
        if (c0 + KC < Cn) {
            const float* sp = src + (size_t)(c0 + KC) * (Hn * Wn);
            const float* tp = tgt + (size_t)(c0 + KC) * (Hn * Wn);
#pragma unroll
            for (int i = 0; i < 10; i++) pf_s[i] = s_ok[i] ? __ldg(sp + s_off[i]) : 0.f;
#pragma unroll
            for (int i = 0; i < 6; i++)  pf_t[i] = t_ok[i] ? __ldg(tp + t_off[i]) : 0.f;
        }

        // compute from shared: per channel, 108 FMAs vs 160 B of LDS
#pragma unroll
        for (int cc = 0; cc < KC; cc++) {
            float tt[4];
            *(float4*)tt = *(const float4*)&s_tgt[cc][ty][tx * 4];
#pragma unroll
            for (int r = 0; r < 3; r++) {
                const float* wp = &s_src[cc][ty + tz * 3 + r][tx * 4];
                float win[12];
                *(float4*)&win[0] = *(const float4*)(wp);
                *(float4*)&win[4] = *(const float4*)(wp + 4);
                *(float4*)&win[8] = *(const float4*)(wp + 8);
#pragma unroll
                for (int dw = 0; dw < 9; dw++)
#pragma unroll
                    for (int p = 0; p < 4; p++)
                        acc[r][dw][p] = fmaf(tt[p], win[dw + p], acc[r][dw][p]);
            }
        }
        __syncthreads();
    }

    // ---- fused relu + L2-normalize over the 81 displacement channels ----
    float part[4] = {0.f, 0.f, 0.f, 0.f};
#pragma unroll
    for (int r = 0; r < 3; r++)
#pragma unroll
        for (int dw = 0; dw < 9; dw++)
#pragma unroll
            for (int p = 0; p < 4; p++) {
                float v = fmaxf(acc[r][dw][p], 0.f);
                acc[r][dw][p] = v;
                part[p] = fmaf(v, v, part[p]);
            }
#pragma unroll
    for (int p = 0; p < 4; p++) s_red[tz][ty][tx * 4 + p] = part[p];
    __syncthreads();

    float inv[4];
#pragma unroll
    for (int p = 0; p < 4; p++) {
        float s = s_red[0][ty][tx * 4 + p]
                + s_red[1][ty][tx * 4 + p]
                + s_red[2][ty][tx * 4 + p];
        inv[p] = 1.f / fmaxf(sqrtf(s), 1e-12f);
    }

    const int h = h0 + ty;
    const int w = wb + tx * 4;
#pragma unroll
    for (int r = 0; r < 3; r++) {
        int dh = tz * 3 + r;
#pragma unroll
        for (int dw = 0; dw < 9; dw++) {
            int d = dh * 9 + dw;
            float4 o;
            o.x = acc[r][dw][0] * inv[0];
            o.y = acc[r][dw][1] * inv[1];
            o.z = acc[r][dw][2] * inv[2];
            o.w = acc[r][dw][3] * inv[3];
            *(float4*)&out[(((size_t)b * 81 + d) * Hn + h) * Wn + w] = o;
        }
    }
}

extern "C" void kernel_launch(void* const* d_in, const int* in_sizes, int n_in,
                              void* d_out, int out_size)
{
    const float* src = (const float*)d_in[0];   // feature_source [16,256,128,128]
    const float* tgt = (const float*)d_in[1];   // feature_target [16,256,128,128]
    float* out = (float*)d_out;                 // [16,81,128,128]

    dim3 grid(Wn / TW, Hn / TH, Bn);            // (4, 8, 16)
    dim3 block(8, 16, 3);                       // 384 threads
    corr_norm_kernel<<<grid, block>>>(src, tgt, out);
}